// round 12
// baseline (speedup 1.0000x reference)
#include <cuda_runtime.h>
#include <cstdint>

#define NN 100000
#define EE 1600000
#define CH0 50048   // chunk boundary, multiple of 128 (gemm2 block rows)

// ---------------- scratch (static __device__, allocation-free) ----------------
__device__ __align__(16) float g_y1[(size_t)NN * 128];   // x @ w1_rel
__device__ __align__(16) float g_h [(size_t)NN * 128];   // h = x@w1_root + b1 + agg
__device__ __align__(16) float g_y2[(size_t)NN * 64];    // relu(h) @ w2_rel
__device__ int   g_deg[NN];
__device__ int   g_rowstart[NN + 1];
__device__ int   g_cursor[NN];
__device__ int   g_csr[EE];                // src node ids grouped by dst
__device__ int   g_bsum[128];
__device__ int   g_is64;                   // edge_index dtype flag

// ---------------- packed fp32x2 FMA helpers ----------------
__device__ __forceinline__ void ffma2(unsigned long long& acc,
                                      unsigned long long a,
                                      unsigned long long b) {
    asm("fma.rn.f32x2 %0, %1, %2, %0;" : "+l"(acc) : "l"(a), "l"(b));
}
__device__ __forceinline__ float2 unpack2(unsigned long long v) {
    float2 r;
    asm("mov.b64 {%0, %1}, %2;" : "=f"(r.x), "=f"(r.y) : "l"(v));
    return r;
}

// ---------------- dtype probe + deg init (merged) ----------------
// int64 edge ids < 2^31 have zero high words at every odd 32-bit position.
__global__ void k_init(const int* __restrict__ ei32) {
    int i = blockIdx.x * blockDim.x + threadIdx.x;
    if (i < NN) g_deg[i] = 0;
    if (blockIdx.x == 0 && threadIdx.x == 0) {
        int is64 = 1;
        #pragma unroll
        for (int q = 0; q < 16; q++)
            if (ei32[8 * q + 1] != 0) is64 = 0;
        g_is64 = is64;
    }
}

__device__ __forceinline__ int edge_src(const int* ei32, int e, int is64) {
    return is64 ? ei32[2 * e] : ei32[e];
}
__device__ __forceinline__ int edge_dst(const int* ei32, int e, int is64) {
    return is64 ? ei32[2 * (EE + e)] : ei32[EE + e];
}

// ---------------- CSR build ----------------
__global__ void k_hist(const int* __restrict__ ei32) {
    int e = blockIdx.x * blockDim.x + threadIdx.x;
    if (e < EE) {
        int d = edge_dst(ei32, e, g_is64);
        atomicAdd(&g_deg[d], 1);
    }
}

// block-local exclusive scan over 1024 elems/block (4 per thread)
__global__ void k_scanA() {
    __shared__ int wsum[8];
    int t = threadIdx.x;
    int base = blockIdx.x * 1024 + t * 4;
    int v0 = (base + 0 < NN) ? g_deg[base + 0] : 0;
    int v1 = (base + 1 < NN) ? g_deg[base + 1] : 0;
    int v2 = (base + 2 < NN) ? g_deg[base + 2] : 0;
    int v3 = (base + 3 < NN) ? g_deg[base + 3] : 0;
    int ts = v0 + v1 + v2 + v3;
    int lane = t & 31, wid = t >> 5;
    int s = ts;
    #pragma unroll
    for (int o = 1; o < 32; o <<= 1) {
        int n = __shfl_up_sync(0xffffffffu, s, o);
        if (lane >= o) s += n;
    }
    if (lane == 31) wsum[wid] = s;
    __syncthreads();
    if (wid == 0) {
        int a = (lane < 8) ? wsum[lane] : 0;
        #pragma unroll
        for (int o = 1; o < 8; o <<= 1) {
            int n = __shfl_up_sync(0xffffffffu, a, o);
            if (lane >= o) a += n;
        }
        if (lane < 8) wsum[lane] = a;
    }
    __syncthreads();
    int excl = (wid ? wsum[wid - 1] : 0) + (s - ts);
    if (base + 0 < NN) g_rowstart[base + 0] = excl;
    if (base + 1 < NN) g_rowstart[base + 1] = excl + v0;
    if (base + 2 < NN) g_rowstart[base + 2] = excl + v0 + v1;
    if (base + 3 < NN) g_rowstart[base + 3] = excl + v0 + v1 + v2;
    if (t == 0) g_bsum[blockIdx.x] = wsum[7];
}

// exclusive scan of the 98 block sums (single block)
__global__ void k_scanB() {
    __shared__ int ws[4];
    int t = threadIdx.x;
    int v = (t < 98) ? g_bsum[t] : 0;
    int lane = t & 31, wid = t >> 5;
    int s = v;
    #pragma unroll
    for (int o = 1; o < 32; o <<= 1) {
        int n = __shfl_up_sync(0xffffffffu, s, o);
        if (lane >= o) s += n;
    }
    if (lane == 31) ws[wid] = s;
    __syncthreads();
    if (wid == 0) {
        int a = (lane < 4) ? ws[lane] : 0;
        #pragma unroll
        for (int o = 1; o < 4; o <<= 1) {
            int n = __shfl_up_sync(0xffffffffu, a, o);
            if (lane >= o) a += n;
        }
        if (lane < 4) ws[lane] = a;
    }
    __syncthreads();
    int incl = s + (wid ? ws[wid - 1] : 0);
    if (t < 98) g_bsum[t] = incl - v;
}

// finalize rowstart and seed cursor with it (fill then needs ONE atomic, no extra load)
__global__ void k_scanC() {
    int i = blockIdx.x * blockDim.x + threadIdx.x;
    if (i < NN) {
        int v = g_rowstart[i] + g_bsum[i >> 10];
        g_rowstart[i] = v;
        g_cursor[i] = v;
    }
    if (i == 0) g_rowstart[NN] = EE;
}

__global__ void k_fill(const int* __restrict__ ei32) {
    int e = blockIdx.x * blockDim.x + threadIdx.x;
    if (e < EE) {
        int is64 = g_is64;
        int d = edge_dst(ei32, e, is64);
        int s = edge_src(ei32, e, is64);
        int pos = atomicAdd(&g_cursor[d], 1);
        g_csr[pos] = s;
    }
}

// ---------------- GEMM 1: y1 = x @ w1_rel ; h = x @ w1_root + b1 ----------------
__global__ __launch_bounds__(256) void k_gemm1(const float* __restrict__ x,
                                               const float* __restrict__ w_rel,
                                               const float* __restrict__ w_root,
                                               const float* __restrict__ b1) {
    extern __shared__ float smem[];
    float*  sWrel  = smem;                       // [128][128]
    float*  sWroot = smem + 128 * 128;           // [128][128]
    float2* sXd    = (float2*)(smem + 2 * 128 * 128); // [128][65] duplicated x
    int t = threadIdx.x;

    for (int i = t; i < 128 * 128 / 4; i += 256) {
        ((float4*)sWrel)[i]  = ((const float4*)w_rel)[i];
        ((float4*)sWroot)[i] = ((const float4*)w_root)[i];
    }
    int row0 = blockIdx.x * 64;
    for (int idx = t; idx < 64 * 128; idx += 256) {
        int r = idx >> 7, k = idx & 127;
        int grow = row0 + r;
        float v = (grow < NN) ? x[(size_t)grow * 128 + k] : 0.f;
        sXd[k * 65 + r] = make_float2(v, v);
    }
    __syncthreads();

    int cg = t & 31, rg = t >> 5;
    unsigned long long acc[8][4];
    #pragma unroll
    for (int i = 0; i < 8; i++)
        #pragma unroll
        for (int j = 0; j < 4; j++) acc[i][j] = 0ull;

    const float* wrp = sWrel + cg * 4;
    const float* wop = sWroot + cg * 4;
    const unsigned long long* xp = (const unsigned long long*)sXd + rg * 8;

    #pragma unroll 4
    for (int k = 0; k < 128; k++) {
        ulonglong2 wr = *(const ulonglong2*)(wrp + k * 128);
        ulonglong2 wo = *(const ulonglong2*)(wop + k * 128);
        #pragma unroll
        for (int rr = 0; rr < 8; rr++) {
            unsigned long long xv = xp[k * 65 + rr];
            ffma2(acc[rr][0], xv, wr.x);
            ffma2(acc[rr][1], xv, wr.y);
            ffma2(acc[rr][2], xv, wo.x);
            ffma2(acc[rr][3], xv, wo.y);
        }
    }

    float4 bias = *(const float4*)(b1 + cg * 4);
    #pragma unroll
    for (int rr = 0; rr < 8; rr++) {
        int row = row0 + rg * 8 + rr;
        if (row >= NN) break;
        float2 a0 = unpack2(acc[rr][0]), a1 = unpack2(acc[rr][1]);
        *(float4*)(g_y1 + (size_t)row * 128 + cg * 4) =
            make_float4(a0.x, a0.y, a1.x, a1.y);
        float2 r0 = unpack2(acc[rr][2]), r1 = unpack2(acc[rr][3]);
        *(float4*)(g_h + (size_t)row * 128 + cg * 4) =
            make_float4(r0.x + bias.x, r0.y + bias.y, r1.x + bias.z, r1.y + bias.w);
    }
}

// ---------------- gather layer 1 (chunked): h[n] += sum_{src->n} y1[src] ----------------
__global__ void k_gather1(int wbase, int wend) {
    int w = wbase + ((blockIdx.x * blockDim.x + threadIdx.x) >> 5);
    if (w >= wend) return;
    int lane = threadIdx.x & 31;
    int beg = g_rowstart[w], end = g_rowstart[w + 1];
    float4 a0 = make_float4(0, 0, 0, 0), a1 = make_float4(0, 0, 0, 0);
    int j = beg;
    for (; j + 1 < end; j += 2) {
        int s0 = __ldg(&g_csr[j]);
        int s1 = __ldg(&g_csr[j + 1]);
        float4 v0 = *(const float4*)(g_y1 + (size_t)s0 * 128 + lane * 4);
        float4 v1 = *(const float4*)(g_y1 + (size_t)s1 * 128 + lane * 4);
        a0.x += v0.x; a0.y += v0.y; a0.z += v0.z; a0.w += v0.w;
        a1.x += v1.x; a1.y += v1.y; a1.z += v1.z; a1.w += v1.w;
    }
    if (j < end) {
        int s = __ldg(&g_csr[j]);
        float4 v = *(const float4*)(g_y1 + (size_t)s * 128 + lane * 4);
        a0.x += v.x; a0.y += v.y; a0.z += v.z; a0.w += v.w;
    }
    float* hp = g_h + (size_t)w * 128 + lane * 4;
    float4 hv = *(float4*)hp;
    hv.x += a0.x + a1.x; hv.y += a0.y + a1.y;
    hv.z += a0.z + a1.z; hv.w += a0.w + a1.w;
    *(float4*)hp = hv;
}

// ---------------- GEMM 2 (chunked): y2 = relu(h) @ w2_rel ; out = relu(h) @ w2_root + b2 --
__global__ __launch_bounds__(256) void k_gemm2(const float* __restrict__ w_rel,
                                               const float* __restrict__ w_root,
                                               const float* __restrict__ b2,
                                               float* __restrict__ out, int blk0) {
    extern __shared__ float smem[];
    float*  sWrel  = smem;                      // [128][64]
    float*  sWroot = smem + 128 * 64;
    float2* sXd    = (float2*)(smem + 2 * 128 * 64); // [128][129]
    int t = threadIdx.x;

    for (int i = t; i < 128 * 64 / 4; i += 256) {
        ((float4*)sWrel)[i]  = ((const float4*)w_rel)[i];
        ((float4*)sWroot)[i] = ((const float4*)w_root)[i];
    }
    int row0 = (blk0 + blockIdx.x) * 128;
    for (int idx = t; idx < 128 * 128; idx += 256) {
        int r = idx >> 7, k = idx & 127;
        int grow = row0 + r;
        float v = (grow < NN) ? g_h[(size_t)grow * 128 + k] : 0.f;
        v = fmaxf(v, 0.f);
        sXd[k * 129 + r] = make_float2(v, v);
    }
    __syncthreads();

    int cg = t & 15, rg = t >> 4;
    unsigned long long acc[8][4];
    #pragma unroll
    for (int i = 0; i < 8; i++)
        #pragma unroll
        for (int j = 0; j < 4; j++) acc[i][j] = 0ull;

    const float* wrp = sWrel + cg * 4;
    const float* wop = sWroot + cg * 4;
    const unsigned long long* xp = (const unsigned long long*)sXd + rg * 8;

    #pragma unroll 4
    for (int k = 0; k < 128; k++) {
        ulonglong2 wr = *(const ulonglong2*)(wrp + k * 64);
        ulonglong2 wo = *(const ulonglong2*)(wop + k * 64);
        #pragma unroll
        for (int rr = 0; rr < 8; rr++) {
            unsigned long long xv = xp[k * 129 + rr];
            ffma2(acc[rr][0], xv, wr.x);
            ffma2(acc[rr][1], xv, wr.y);
            ffma2(acc[rr][2], xv, wo.x);
            ffma2(acc[rr][3], xv, wo.y);
        }
    }

    float4 bias = *(const float4*)(b2 + cg * 4);
    #pragma unroll
    for (int rr = 0; rr < 8; rr++) {
        int row = row0 + rg * 8 + rr;
        if (row >= NN) break;
        float2 a0 = unpack2(acc[rr][0]), a1 = unpack2(acc[rr][1]);
        *(float4*)(g_y2 + (size_t)row * 64 + cg * 4) =
            make_float4(a0.x, a0.y, a1.x, a1.y);
        float2 r0 = unpack2(acc[rr][2]), r1 = unpack2(acc[rr][3]);
        *(float4*)(out + (size_t)row * 64 + cg * 4) =
            make_float4(r0.x + bias.x, r0.y + bias.y, r1.x + bias.z, r1.y + bias.w);
    }
}

// ---------------- gather layer 2: out[n] += sum_{src->n} y2[src] ----------------
__global__ void k_gather2(float* __restrict__ out) {
    int w = (blockIdx.x * blockDim.x + threadIdx.x) >> 5;
    if (w >= NN) return;
    int lane = threadIdx.x & 31;
    int beg = g_rowstart[w], end = g_rowstart[w + 1];
    float2 a0 = make_float2(0, 0), a1 = make_float2(0, 0);
    int j = beg;
    for (; j + 1 < end; j += 2) {
        int s0 = __ldg(&g_csr[j]);
        int s1 = __ldg(&g_csr[j + 1]);
        float2 v0 = *(const float2*)(g_y2 + (size_t)s0 * 64 + lane * 2);
        float2 v1 = *(const float2*)(g_y2 + (size_t)s1 * 64 + lane * 2);
        a0.x += v0.x; a0.y += v0.y;
        a1.x += v1.x; a1.y += v1.y;
    }
    if (j < end) {
        int s = __ldg(&g_csr[j]);
        float2 v = *(const float2*)(g_y2 + (size_t)s * 64 + lane * 2);
        a0.x += v.x; a0.y += v.y;
    }
    float* op = out + (size_t)w * 64 + lane * 2;
    float2 ov = *(float2*)op;
    ov.x += a0.x + a1.x;
    ov.y += a0.y + a1.y;
    *(float2*)op = ov;
}

// ---------------- launch ----------------
extern "C" void kernel_launch(void* const* d_in, const int* in_sizes, int n_in,
                              void* d_out, int out_size) {
    const float* x       = (const float*)d_in[0];
    const int*   ei32    = (const int*)d_in[1];
    const float* w1_rel  = (const float*)d_in[2];
    const float* b1      = (const float*)d_in[3];
    const float* w1_root = (const float*)d_in[4];
    const float* w2_rel  = (const float*)d_in[5];
    const float* b2      = (const float*)d_in[6];
    const float* w2_root = (const float*)d_in[7];
    float*       out     = (float*)d_out;

    static cudaStream_t s_side = nullptr;
    static cudaEvent_t  e_fork = nullptr, e_csr = nullptr, e_g1 = nullptr, e_g1c1 = nullptr;
    if (s_side == nullptr) {
        cudaStreamCreateWithFlags(&s_side, cudaStreamNonBlocking);
        cudaEventCreateWithFlags(&e_fork, cudaEventDisableTiming);
        cudaEventCreateWithFlags(&e_csr,  cudaEventDisableTiming);
        cudaEventCreateWithFlags(&e_g1,   cudaEventDisableTiming);
        cudaEventCreateWithFlags(&e_g1c1, cudaEventDisableTiming);
    }

    const int SMEM1 = 2 * 128 * 128 * 4 + 128 * 65 * 8;   // 197632
    const int SMEM2 = 2 * 128 * 64 * 4 + 128 * 129 * 8;   // 197632
    cudaFuncSetAttribute(k_gemm1, cudaFuncAttributeMaxDynamicSharedMemorySize, SMEM1);
    cudaFuncSetAttribute(k_gemm2, cudaFuncAttributeMaxDynamicSharedMemorySize, SMEM2);

    // fork side stream
    cudaEventRecord(e_fork, 0);
    cudaStreamWaitEvent(s_side, e_fork, 0);

    // issue order chosen so k_gemm1 is the 4th kernel launch (ncu profiles index 3)
    k_init <<<(NN + 255) / 256, 256, 0, s_side>>>(ei32);        // 0
    k_hist <<<(EE + 255) / 256, 256, 0, s_side>>>(ei32);        // 1
    k_scanA<<<(NN + 1023) / 1024, 256, 0, s_side>>>();          // 2
    k_gemm1<<<(NN + 63) / 64, 256, SMEM1>>>(x, w1_rel, w1_root, b1);   // 3  <- profiled
    k_scanB<<<1, 128, 0, s_side>>>();                           // 4
    k_scanC<<<(NN + 255) / 256, 256, 0, s_side>>>();            // 5
    k_fill <<<(EE + 255) / 256, 256, 0, s_side>>>(ei32);        // 6
    cudaEventRecord(e_csr, s_side);
    cudaEventRecord(e_g1, 0);                                   // gemm1 done (main)

    // chunk 0 on main: gather1 then gemm2
    cudaStreamWaitEvent(0, e_csr, 0);
    k_gather1<<<(CH0 * 32 + 255) / 256, 256>>>(0, CH0);         // 7
    k_gemm2  <<<CH0 / 128, 256, SMEM2>>>(w2_rel, w2_root, b2, out, 0);   // 8

    // chunk 1 gather on side (needs CSR: program order; gemm1: e_g1)
    cudaStreamWaitEvent(s_side, e_g1, 0);
    k_gather1<<<((NN - CH0) * 32 + 255) / 256, 256, 0, s_side>>>(CH0, NN);   // 9
    cudaEventRecord(e_g1c1, s_side);

    // chunk 1 gemm2 on main after side gather done
    cudaStreamWaitEvent(0, e_g1c1, 0);
    k_gemm2<<<(NN + 127) / 128 - CH0 / 128, 256, SMEM2>>>(w2_rel, w2_root, b2, out, CH0 / 128);  // 10

    // final gather (needs all y2; main program order covers both gemm2 chunks)
    k_gather2<<<(NN * 32 + 255) / 256, 256>>>(out);             // 11
}

// round 13
// speedup vs baseline: 1.0147x; 1.0147x over previous
#include <cuda_runtime.h>
#include <cstdint>

#define NN 100000
#define EE 1600000
#define CH0 50048   // chunk boundary, multiple of 128 (gemm2 block rows)

// ---------------- scratch (static __device__, allocation-free) ----------------
__device__ __align__(16) float g_y1[(size_t)NN * 128];   // x @ w1_rel
__device__ __align__(16) float g_h [(size_t)NN * 128];   // h = x@w1_root + b1 + agg
__device__ __align__(16) float g_y2[(size_t)NN * 64];    // relu(h) @ w2_rel
__device__ int   g_deg[NN];
__device__ int   g_rowstart[NN + 1];
__device__ int   g_cursor[NN];
__device__ int   g_csr[EE];                // src node ids grouped by dst
__device__ int   g_bsum[128];
__device__ int   g_is64;                   // edge_index dtype flag

// ---------------- packed fp32x2 FMA helpers ----------------
__device__ __forceinline__ void ffma2(unsigned long long& acc,
                                      unsigned long long a,
                                      unsigned long long b) {
    asm("fma.rn.f32x2 %0, %1, %2, %0;" : "+l"(acc) : "l"(a), "l"(b));
}
__device__ __forceinline__ float2 unpack2(unsigned long long v) {
    float2 r;
    asm("mov.b64 {%0, %1}, %2;" : "=f"(r.x), "=f"(r.y) : "l"(v));
    return r;
}

// ---------------- dtype probe + deg init (merged) ----------------
__global__ void k_init(const int* __restrict__ ei32) {
    int i = blockIdx.x * blockDim.x + threadIdx.x;
    if (i < NN) g_deg[i] = 0;
    if (blockIdx.x == 0 && threadIdx.x == 0) {
        int is64 = 1;
        #pragma unroll
        for (int q = 0; q < 16; q++)
            if (ei32[8 * q + 1] != 0) is64 = 0;
        g_is64 = is64;
    }
}

__device__ __forceinline__ int edge_src(const int* ei32, int e, int is64) {
    return is64 ? ei32[2 * e] : ei32[e];
}
__device__ __forceinline__ int edge_dst(const int* ei32, int e, int is64) {
    return is64 ? ei32[2 * (EE + e)] : ei32[EE + e];
}

// ---------------- CSR build ----------------
__global__ void k_hist(const int* __restrict__ ei32) {
    int e = blockIdx.x * blockDim.x + threadIdx.x;
    if (e < EE) {
        int d = edge_dst(ei32, e, g_is64);
        atomicAdd(&g_deg[d], 1);
    }
}

__global__ void k_scanA() {
    __shared__ int wsum[8];
    int t = threadIdx.x;
    int base = blockIdx.x * 1024 + t * 4;
    int v0 = (base + 0 < NN) ? g_deg[base + 0] : 0;
    int v1 = (base + 1 < NN) ? g_deg[base + 1] : 0;
    int v2 = (base + 2 < NN) ? g_deg[base + 2] : 0;
    int v3 = (base + 3 < NN) ? g_deg[base + 3] : 0;
    int ts = v0 + v1 + v2 + v3;
    int lane = t & 31, wid = t >> 5;
    int s = ts;
    #pragma unroll
    for (int o = 1; o < 32; o <<= 1) {
        int n = __shfl_up_sync(0xffffffffu, s, o);
        if (lane >= o) s += n;
    }
    if (lane == 31) wsum[wid] = s;
    __syncthreads();
    if (wid == 0) {
        int a = (lane < 8) ? wsum[lane] : 0;
        #pragma unroll
        for (int o = 1; o < 8; o <<= 1) {
            int n = __shfl_up_sync(0xffffffffu, a, o);
            if (lane >= o) a += n;
        }
        if (lane < 8) wsum[lane] = a;
    }
    __syncthreads();
    int excl = (wid ? wsum[wid - 1] : 0) + (s - ts);
    if (base + 0 < NN) g_rowstart[base + 0] = excl;
    if (base + 1 < NN) g_rowstart[base + 1] = excl + v0;
    if (base + 2 < NN) g_rowstart[base + 2] = excl + v0 + v1;
    if (base + 3 < NN) g_rowstart[base + 3] = excl + v0 + v1 + v2;
    if (t == 0) g_bsum[blockIdx.x] = wsum[7];
}

__global__ void k_scanB() {
    __shared__ int ws[4];
    int t = threadIdx.x;
    int v = (t < 98) ? g_bsum[t] : 0;
    int lane = t & 31, wid = t >> 5;
    int s = v;
    #pragma unroll
    for (int o = 1; o < 32; o <<= 1) {
        int n = __shfl_up_sync(0xffffffffu, s, o);
        if (lane >= o) s += n;
    }
    if (lane == 31) ws[wid] = s;
    __syncthreads();
    if (wid == 0) {
        int a = (lane < 4) ? ws[lane] : 0;
        #pragma unroll
        for (int o = 1; o < 4; o <<= 1) {
            int n = __shfl_up_sync(0xffffffffu, a, o);
            if (lane >= o) a += n;
        }
        if (lane < 4) ws[lane] = a;
    }
    __syncthreads();
    int incl = s + (wid ? ws[wid - 1] : 0);
    if (t < 98) g_bsum[t] = incl - v;
}

// finalize rowstart and seed cursor (fill needs ONE atomic, no extra load)
__global__ void k_scanC() {
    int i = blockIdx.x * blockDim.x + threadIdx.x;
    if (i < NN) {
        int v = g_rowstart[i] + g_bsum[i >> 10];
        g_rowstart[i] = v;
        g_cursor[i] = v;
    }
    if (i == 0) g_rowstart[NN] = EE;
}

__global__ void k_fill(const int* __restrict__ ei32) {
    int e = blockIdx.x * blockDim.x + threadIdx.x;
    if (e < EE) {
        int is64 = g_is64;
        int d = edge_dst(ei32, e, is64);
        int s = edge_src(ei32, e, is64);
        int pos = atomicAdd(&g_cursor[d], 1);
        g_csr[pos] = s;
    }
}

// ---------------- GEMM 1: y1 = x @ w1_rel ; h = x @ w1_root + b1 ----------------
// block = 512 threads (16 warps = 4/SMSP for latency hiding), 64 rows/block.
// Each thread: 4 rows x 8 cols (acc[4][4] f32x2). smem unchanged (197632 B).
__global__ __launch_bounds__(512) void k_gemm1(const float* __restrict__ x,
                                               const float* __restrict__ w_rel,
                                               const float* __restrict__ w_root,
                                               const float* __restrict__ b1) {
    extern __shared__ float smem[];
    float*  sWrel  = smem;                       // [128][128]
    float*  sWroot = smem + 128 * 128;           // [128][128]
    float2* sXd    = (float2*)(smem + 2 * 128 * 128); // [128][65] duplicated x
    int t = threadIdx.x;

    for (int i = t; i < 128 * 128 / 4; i += 512) {
        ((float4*)sWrel)[i]  = ((const float4*)w_rel)[i];
        ((float4*)sWroot)[i] = ((const float4*)w_root)[i];
    }
    int row0 = blockIdx.x * 64;
    for (int idx = t; idx < 64 * 128; idx += 512) {
        int r = idx >> 7, k = idx & 127;
        int grow = row0 + r;
        float v = (grow < NN) ? x[(size_t)grow * 128 + k] : 0.f;
        sXd[k * 65 + r] = make_float2(v, v);
    }
    __syncthreads();

    int cg = t & 31, rg = t >> 5;   // 32 col groups x 16 row groups (4 rows each)
    unsigned long long acc[4][4];
    #pragma unroll
    for (int i = 0; i < 4; i++)
        #pragma unroll
        for (int j = 0; j < 4; j++) acc[i][j] = 0ull;

    const float* wrp = sWrel + cg * 4;
    const float* wop = sWroot + cg * 4;
    const unsigned long long* xp = (const unsigned long long*)sXd + rg * 4;

    #pragma unroll 4
    for (int k = 0; k < 128; k++) {
        ulonglong2 wr = *(const ulonglong2*)(wrp + k * 128);
        ulonglong2 wo = *(const ulonglong2*)(wop + k * 128);
        #pragma unroll
        for (int rr = 0; rr < 4; rr++) {
            unsigned long long xv = xp[k * 65 + rr];
            ffma2(acc[rr][0], xv, wr.x);
            ffma2(acc[rr][1], xv, wr.y);
            ffma2(acc[rr][2], xv, wo.x);
            ffma2(acc[rr][3], xv, wo.y);
        }
    }

    float4 bias = *(const float4*)(b1 + cg * 4);
    #pragma unroll
    for (int rr = 0; rr < 4; rr++) {
        int row = row0 + rg * 4 + rr;
        if (row >= NN) break;
        float2 a0 = unpack2(acc[rr][0]), a1 = unpack2(acc[rr][1]);
        *(float4*)(g_y1 + (size_t)row * 128 + cg * 4) =
            make_float4(a0.x, a0.y, a1.x, a1.y);
        float2 r0 = unpack2(acc[rr][2]), r1 = unpack2(acc[rr][3]);
        *(float4*)(g_h + (size_t)row * 128 + cg * 4) =
            make_float4(r0.x + bias.x, r0.y + bias.y, r1.x + bias.z, r1.y + bias.w);
    }
}

// ---------------- gather layer 1 (chunked): h[n] += sum_{src->n} y1[src] ----------------
__global__ void k_gather1(int wbase, int wend) {
    int w = wbase + ((blockIdx.x * blockDim.x + threadIdx.x) >> 5);
    if (w >= wend) return;
    int lane = threadIdx.x & 31;
    int beg = g_rowstart[w], end = g_rowstart[w + 1];
    float4 a0 = make_float4(0, 0, 0, 0), a1 = make_float4(0, 0, 0, 0);
    int j = beg;
    for (; j + 1 < end; j += 2) {
        int s0 = __ldg(&g_csr[j]);
        int s1 = __ldg(&g_csr[j + 1]);
        float4 v0 = *(const float4*)(g_y1 + (size_t)s0 * 128 + lane * 4);
        float4 v1 = *(const float4*)(g_y1 + (size_t)s1 * 128 + lane * 4);
        a0.x += v0.x; a0.y += v0.y; a0.z += v0.z; a0.w += v0.w;
        a1.x += v1.x; a1.y += v1.y; a1.z += v1.z; a1.w += v1.w;
    }
    if (j < end) {
        int s = __ldg(&g_csr[j]);
        float4 v = *(const float4*)(g_y1 + (size_t)s * 128 + lane * 4);
        a0.x += v.x; a0.y += v.y; a0.z += v.z; a0.w += v.w;
    }
    float* hp = g_h + (size_t)w * 128 + lane * 4;
    float4 hv = *(float4*)hp;
    hv.x += a0.x + a1.x; hv.y += a0.y + a1.y;
    hv.z += a0.z + a1.z; hv.w += a0.w + a1.w;
    *(float4*)hp = hv;
}

// ---------------- GEMM 2 (chunked): y2 = relu(h) @ w2_rel ; out = relu(h) @ w2_root + b2 --
// block = 512 threads, 128 rows/block. Each thread: 4 rows x 8 cols.
__global__ __launch_bounds__(512) void k_gemm2(const float* __restrict__ w_rel,
                                               const float* __restrict__ w_root,
                                               const float* __restrict__ b2,
                                               float* __restrict__ out, int blk0) {
    extern __shared__ float smem[];
    float*  sWrel  = smem;                      // [128][64]
    float*  sWroot = smem + 128 * 64;
    float2* sXd    = (float2*)(smem + 2 * 128 * 64); // [128][129]
    int t = threadIdx.x;

    for (int i = t; i < 128 * 64 / 4; i += 512) {
        ((float4*)sWrel)[i]  = ((const float4*)w_rel)[i];
        ((float4*)sWroot)[i] = ((const float4*)w_root)[i];
    }
    int row0 = (blk0 + blockIdx.x) * 128;
    for (int idx = t; idx < 128 * 128; idx += 512) {
        int r = idx >> 7, k = idx & 127;
        int grow = row0 + r;
        float v = (grow < NN) ? g_h[(size_t)grow * 128 + k] : 0.f;
        v = fmaxf(v, 0.f);
        sXd[k * 129 + r] = make_float2(v, v);
    }
    __syncthreads();

    int cg = t & 15, rg = t >> 4;   // 16 col groups x 32 row groups (4 rows each)
    unsigned long long acc[4][4];
    #pragma unroll
    for (int i = 0; i < 4; i++)
        #pragma unroll
        for (int j = 0; j < 4; j++) acc[i][j] = 0ull;

    const float* wrp = sWrel + cg * 4;
    const float* wop = sWroot + cg * 4;
    const unsigned long long* xp = (const unsigned long long*)sXd + rg * 4;

    #pragma unroll 4
    for (int k = 0; k < 128; k++) {
        ulonglong2 wr = *(const ulonglong2*)(wrp + k * 64);
        ulonglong2 wo = *(const ulonglong2*)(wop + k * 64);
        #pragma unroll
        for (int rr = 0; rr < 4; rr++) {
            unsigned long long xv = xp[k * 129 + rr];
            ffma2(acc[rr][0], xv, wr.x);
            ffma2(acc[rr][1], xv, wr.y);
            ffma2(acc[rr][2], xv, wo.x);
            ffma2(acc[rr][3], xv, wo.y);
        }
    }

    float4 bias = *(const float4*)(b2 + cg * 4);
    #pragma unroll
    for (int rr = 0; rr < 4; rr++) {
        int row = row0 + rg * 4 + rr;
        if (row >= NN) break;
        float2 a0 = unpack2(acc[rr][0]), a1 = unpack2(acc[rr][1]);
        *(float4*)(g_y2 + (size_t)row * 64 + cg * 4) =
            make_float4(a0.x, a0.y, a1.x, a1.y);
        float2 r0 = unpack2(acc[rr][2]), r1 = unpack2(acc[rr][3]);
        *(float4*)(out + (size_t)row * 64 + cg * 4) =
            make_float4(r0.x + bias.x, r0.y + bias.y, r1.x + bias.z, r1.y + bias.w);
    }
}

// ---------------- gather layer 2: out[n] += sum_{src->n} y2[src] ----------------
__global__ void k_gather2(float* __restrict__ out) {
    int w = (blockIdx.x * blockDim.x + threadIdx.x) >> 5;
    if (w >= NN) return;
    int lane = threadIdx.x & 31;
    int beg = g_rowstart[w], end = g_rowstart[w + 1];
    float2 a0 = make_float2(0, 0), a1 = make_float2(0, 0);
    int j = beg;
    for (; j + 1 < end; j += 2) {
        int s0 = __ldg(&g_csr[j]);
        int s1 = __ldg(&g_csr[j + 1]);
        float2 v0 = *(const float2*)(g_y2 + (size_t)s0 * 64 + lane * 2);
        float2 v1 = *(const float2*)(g_y2 + (size_t)s1 * 64 + lane * 2);
        a0.x += v0.x; a0.y += v0.y;
        a1.x += v1.x; a1.y += v1.y;
    }
    if (j < end) {
        int s = __ldg(&g_csr[j]);
        float2 v = *(const float2*)(g_y2 + (size_t)s * 64 + lane * 2);
        a0.x += v.x; a0.y += v.y;
    }
    float* op = out + (size_t)w * 64 + lane * 2;
    float2 ov = *(float2*)op;
    ov.x += a0.x + a1.x;
    ov.y += a0.y + a1.y;
    *(float2*)op = ov;
}

// ---------------- launch ----------------
extern "C" void kernel_launch(void* const* d_in, const int* in_sizes, int n_in,
                              void* d_out, int out_size) {
    const float* x       = (const float*)d_in[0];
    const int*   ei32    = (const int*)d_in[1];
    const float* w1_rel  = (const float*)d_in[2];
    const float* b1      = (const float*)d_in[3];
    const float* w1_root = (const float*)d_in[4];
    const float* w2_rel  = (const float*)d_in[5];
    const float* b2      = (const float*)d_in[6];
    const float* w2_root = (const float*)d_in[7];
    float*       out     = (float*)d_out;

    static cudaStream_t s_side = nullptr;
    static cudaEvent_t  e_fork = nullptr, e_csr = nullptr, e_g1 = nullptr, e_g1c1 = nullptr;
    if (s_side == nullptr) {
        cudaStreamCreateWithFlags(&s_side, cudaStreamNonBlocking);
        cudaEventCreateWithFlags(&e_fork, cudaEventDisableTiming);
        cudaEventCreateWithFlags(&e_csr,  cudaEventDisableTiming);
        cudaEventCreateWithFlags(&e_g1,   cudaEventDisableTiming);
        cudaEventCreateWithFlags(&e_g1c1, cudaEventDisableTiming);
    }

    const int SMEM1 = 2 * 128 * 128 * 4 + 128 * 65 * 8;   // 197632
    const int SMEM2 = 2 * 128 * 64 * 4 + 128 * 129 * 8;   // 197632
    cudaFuncSetAttribute(k_gemm1, cudaFuncAttributeMaxDynamicSharedMemorySize, SMEM1);
    cudaFuncSetAttribute(k_gemm2, cudaFuncAttributeMaxDynamicSharedMemorySize, SMEM2);

    // fork side stream
    cudaEventRecord(e_fork, 0);
    cudaStreamWaitEvent(s_side, e_fork, 0);

    // issue order: k_gemm1 is the 4th kernel launch (ncu profiles index 3)
    k_init <<<(NN + 255) / 256, 256, 0, s_side>>>(ei32);        // 0
    k_hist <<<(EE + 255) / 256, 256, 0, s_side>>>(ei32);        // 1
    k_scanA<<<(NN + 1023) / 1024, 256, 0, s_side>>>();          // 2
    k_gemm1<<<(NN + 63) / 64, 512, SMEM1>>>(x, w1_rel, w1_root, b1);   // 3  <- profiled
    k_scanB<<<1, 128, 0, s_side>>>();                           // 4
    k_scanC<<<(NN + 255) / 256, 256, 0, s_side>>>();            // 5
    k_fill <<<(EE + 255) / 256, 256, 0, s_side>>>(ei32);        // 6
    cudaEventRecord(e_csr, s_side);
    cudaEventRecord(e_g1, 0);

    // chunk 0 on main: gather1 then gemm2
    cudaStreamWaitEvent(0, e_csr, 0);
    k_gather1<<<(CH0 * 32 + 255) / 256, 256>>>(0, CH0);         // 7
    k_gemm2  <<<CH0 / 128, 512, SMEM2>>>(w2_rel, w2_root, b2, out, 0);   // 8

    // chunk 1 gather on side (needs CSR: program order; gemm1: e_g1)
    cudaStreamWaitEvent(s_side, e_g1, 0);
    k_gather1<<<((NN - CH0) * 32 + 255) / 256, 256, 0, s_side>>>(CH0, NN);   // 9
    cudaEventRecord(e_g1c1, s_side);

    // chunk 1 gemm2 on main after side gather done
    cudaStreamWaitEvent(0, e_g1c1, 0);
    k_gemm2<<<(NN + 127) / 128 - CH0 / 128, 512, SMEM2>>>(w2_rel, w2_root, b2, out, CH0 / 128);  // 10

    // final gather
    k_gather2<<<(NN * 32 + 255) / 256, 256>>>(out);             // 11
}

// round 14
// speedup vs baseline: 1.0283x; 1.0134x over previous
#include <cuda_runtime.h>
#include <cstdint>

#define NN 100000
#define EE 1600000
#define CH0 50048   // chunk boundary, multiple of 128 (gemm2 block rows)

// ---------------- scratch (static __device__, allocation-free) ----------------
__device__ __align__(16) float g_y1[(size_t)NN * 128];   // x @ w1_rel
__device__ __align__(16) float g_h [(size_t)NN * 128];   // h = x@w1_root + b1 + agg
__device__ __align__(16) float g_y2[(size_t)NN * 64];    // relu(h) @ w2_rel
__device__ int   g_deg[NN];
__device__ int   g_rowstart[NN + 1];
__device__ int   g_cursor[NN];
__device__ int   g_csr[EE];                // src node ids grouped by dst
__device__ int   g_bsum[128];
__device__ int   g_is64;                   // edge_index dtype flag

// ---------------- packed fp32x2 FMA helpers ----------------
__device__ __forceinline__ void ffma2(unsigned long long& acc,
                                      unsigned long long a,
                                      unsigned long long b) {
    asm("fma.rn.f32x2 %0, %1, %2, %0;" : "+l"(acc) : "l"(a), "l"(b));
}
__device__ __forceinline__ float2 unpack2(unsigned long long v) {
    float2 r;
    asm("mov.b64 {%0, %1}, %2;" : "=f"(r.x), "=f"(r.y) : "l"(v));
    return r;
}

// ---------------- dtype probe + deg init (merged) ----------------
__global__ void k_init(const int* __restrict__ ei32) {
    int i = blockIdx.x * blockDim.x + threadIdx.x;
    if (i < NN) g_deg[i] = 0;
    if (blockIdx.x == 0 && threadIdx.x == 0) {
        int is64 = 1;
        #pragma unroll
        for (int q = 0; q < 16; q++)
            if (ei32[8 * q + 1] != 0) is64 = 0;
        g_is64 = is64;
    }
}

__device__ __forceinline__ int edge_src(const int* ei32, int e, int is64) {
    return is64 ? ei32[2 * e] : ei32[e];
}
__device__ __forceinline__ int edge_dst(const int* ei32, int e, int is64) {
    return is64 ? ei32[2 * (EE + e)] : ei32[EE + e];
}

// ---------------- CSR build ----------------
__global__ void k_hist(const int* __restrict__ ei32) {
    int e = blockIdx.x * blockDim.x + threadIdx.x;
    if (e < EE) {
        int d = edge_dst(ei32, e, g_is64);
        atomicAdd(&g_deg[d], 1);
    }
}

__global__ void k_scanA() {
    __shared__ int wsum[8];
    int t = threadIdx.x;
    int base = blockIdx.x * 1024 + t * 4;
    int v0 = (base + 0 < NN) ? g_deg[base + 0] : 0;
    int v1 = (base + 1 < NN) ? g_deg[base + 1] : 0;
    int v2 = (base + 2 < NN) ? g_deg[base + 2] : 0;
    int v3 = (base + 3 < NN) ? g_deg[base + 3] : 0;
    int ts = v0 + v1 + v2 + v3;
    int lane = t & 31, wid = t >> 5;
    int s = ts;
    #pragma unroll
    for (int o = 1; o < 32; o <<= 1) {
        int n = __shfl_up_sync(0xffffffffu, s, o);
        if (lane >= o) s += n;
    }
    if (lane == 31) wsum[wid] = s;
    __syncthreads();
    if (wid == 0) {
        int a = (lane < 8) ? wsum[lane] : 0;
        #pragma unroll
        for (int o = 1; o < 8; o <<= 1) {
            int n = __shfl_up_sync(0xffffffffu, a, o);
            if (lane >= o) a += n;
        }
        if (lane < 8) wsum[lane] = a;
    }
    __syncthreads();
    int excl = (wid ? wsum[wid - 1] : 0) + (s - ts);
    if (base + 0 < NN) g_rowstart[base + 0] = excl;
    if (base + 1 < NN) g_rowstart[base + 1] = excl + v0;
    if (base + 2 < NN) g_rowstart[base + 2] = excl + v0 + v1;
    if (base + 3 < NN) g_rowstart[base + 3] = excl + v0 + v1 + v2;
    if (t == 0) g_bsum[blockIdx.x] = wsum[7];
}

__global__ void k_scanB() {
    __shared__ int ws[4];
    int t = threadIdx.x;
    int v = (t < 98) ? g_bsum[t] : 0;
    int lane = t & 31, wid = t >> 5;
    int s = v;
    #pragma unroll
    for (int o = 1; o < 32; o <<= 1) {
        int n = __shfl_up_sync(0xffffffffu, s, o);
        if (lane >= o) s += n;
    }
    if (lane == 31) ws[wid] = s;
    __syncthreads();
    if (wid == 0) {
        int a = (lane < 4) ? ws[lane] : 0;
        #pragma unroll
        for (int o = 1; o < 4; o <<= 1) {
            int n = __shfl_up_sync(0xffffffffu, a, o);
            if (lane >= o) a += n;
        }
        if (lane < 4) ws[lane] = a;
    }
    __syncthreads();
    int incl = s + (wid ? ws[wid - 1] : 0);
    if (t < 98) g_bsum[t] = incl - v;
}

// finalize rowstart and seed cursor (fill needs ONE atomic, no extra load)
__global__ void k_scanC() {
    int i = blockIdx.x * blockDim.x + threadIdx.x;
    if (i < NN) {
        int v = g_rowstart[i] + g_bsum[i >> 10];
        g_rowstart[i] = v;
        g_cursor[i] = v;
    }
    if (i == 0) g_rowstart[NN] = EE;
}

__global__ void k_fill(const int* __restrict__ ei32) {
    int e = blockIdx.x * blockDim.x + threadIdx.x;
    if (e < EE) {
        int is64 = g_is64;
        int d = edge_dst(ei32, e, is64);
        int s = edge_src(ei32, e, is64);
        int pos = atomicAdd(&g_cursor[d], 1);
        g_csr[pos] = s;
    }
}

// ---------------- GEMM 1: y1 = x @ w1_rel ; h = x @ w1_root + b1 ----------------
// 256 threads, 64 rows/block, thread tile 8 rows x 8 cols (acc[8][4] f32x2).
// x staged duplicated (v,v) with stride 66 float2 -> paired rows load as one
// LDS.128 broadcast (16B/crossbar-cycle instead of 8B).
// Crossbar/warp/k = 2x4 (w) + 4x1 (x) = 12 cyc; x8 warps = 96 cyc/k < FMA 128.
__global__ __launch_bounds__(256) void k_gemm1(const float* __restrict__ x,
                                               const float* __restrict__ w_rel,
                                               const float* __restrict__ w_root,
                                               const float* __restrict__ b1) {
    extern __shared__ float smem[];
    float*  sWrel  = smem;                       // [128][128]
    float*  sWroot = smem + 128 * 128;           // [128][128]
    float2* sXd    = (float2*)(smem + 2 * 128 * 128); // [128][66] duplicated x
    int t = threadIdx.x;

    for (int i = t; i < 128 * 128 / 4; i += 256) {
        ((float4*)sWrel)[i]  = ((const float4*)w_rel)[i];
        ((float4*)sWroot)[i] = ((const float4*)w_root)[i];
    }
    int row0 = blockIdx.x * 64;
    for (int idx = t; idx < 64 * 128; idx += 256) {
        int r = idx >> 7, k = idx & 127;
        int grow = row0 + r;
        float v = (grow < NN) ? x[(size_t)grow * 128 + k] : 0.f;
        sXd[k * 66 + r] = make_float2(v, v);
    }
    __syncthreads();

    int cg = t & 31, rg = t >> 5;   // 32 col groups x 8 row groups (8 rows each)
    unsigned long long acc[8][4];
    #pragma unroll
    for (int i = 0; i < 8; i++)
        #pragma unroll
        for (int j = 0; j < 4; j++) acc[i][j] = 0ull;

    const float* wrp = sWrel + cg * 4;
    const float* wop = sWroot + cg * 4;
    const ulonglong2* xp = (const ulonglong2*)(sXd + rg * 8);   // 16B aligned

    #pragma unroll 4
    for (int k = 0; k < 128; k++) {
        ulonglong2 wr = *(const ulonglong2*)(wrp + k * 128);
        ulonglong2 wo = *(const ulonglong2*)(wop + k * 128);
        #pragma unroll
        for (int q = 0; q < 4; q++) {
            ulonglong2 xv = xp[k * 33 + q];     // rows 2q, 2q+1 (dup'd)
            ffma2(acc[2 * q][0], xv.x, wr.x);
            ffma2(acc[2 * q][1], xv.x, wr.y);
            ffma2(acc[2 * q][2], xv.x, wo.x);
            ffma2(acc[2 * q][3], xv.x, wo.y);
            ffma2(acc[2 * q + 1][0], xv.y, wr.x);
            ffma2(acc[2 * q + 1][1], xv.y, wr.y);
            ffma2(acc[2 * q + 1][2], xv.y, wo.x);
            ffma2(acc[2 * q + 1][3], xv.y, wo.y);
        }
    }

    float4 bias = *(const float4*)(b1 + cg * 4);
    #pragma unroll
    for (int rr = 0; rr < 8; rr++) {
        int row = row0 + rg * 8 + rr;
        if (row >= NN) break;
        float2 a0 = unpack2(acc[rr][0]), a1 = unpack2(acc[rr][1]);
        *(float4*)(g_y1 + (size_t)row * 128 + cg * 4) =
            make_float4(a0.x, a0.y, a1.x, a1.y);
        float2 r0 = unpack2(acc[rr][2]), r1 = unpack2(acc[rr][3]);
        *(float4*)(g_h + (size_t)row * 128 + cg * 4) =
            make_float4(r0.x + bias.x, r0.y + bias.y, r1.x + bias.z, r1.y + bias.w);
    }
}

// ---------------- gather layer 1 (chunked): h[n] += sum_{src->n} y1[src] ----------------
__global__ void k_gather1(int wbase, int wend) {
    int w = wbase + ((blockIdx.x * blockDim.x + threadIdx.x) >> 5);
    if (w >= wend) return;
    int lane = threadIdx.x & 31;
    int beg = g_rowstart[w], end = g_rowstart[w + 1];
    float4 a0 = make_float4(0, 0, 0, 0), a1 = make_float4(0, 0, 0, 0);
    int j = beg;
    for (; j + 1 < end; j += 2) {
        int s0 = __ldg(&g_csr[j]);
        int s1 = __ldg(&g_csr[j + 1]);
        float4 v0 = *(const float4*)(g_y1 + (size_t)s0 * 128 + lane * 4);
        float4 v1 = *(const float4*)(g_y1 + (size_t)s1 * 128 + lane * 4);
        a0.x += v0.x; a0.y += v0.y; a0.z += v0.z; a0.w += v0.w;
        a1.x += v1.x; a1.y += v1.y; a1.z += v1.z; a1.w += v1.w;
    }
    if (j < end) {
        int s = __ldg(&g_csr[j]);
        float4 v = *(const float4*)(g_y1 + (size_t)s * 128 + lane * 4);
        a0.x += v.x; a0.y += v.y; a0.z += v.z; a0.w += v.w;
    }
    float* hp = g_h + (size_t)w * 128 + lane * 4;
    float4 hv = *(float4*)hp;
    hv.x += a0.x + a1.x; hv.y += a0.y + a1.y;
    hv.z += a0.z + a1.z; hv.w += a0.w + a1.w;
    *(float4*)hp = hv;
}

// ---------------- GEMM 2 (chunked): y2 = relu(h) @ w2_rel ; out = relu(h) @ w2_root + b2 --
// 256 threads, 128 rows/block, thread tile 8 rows x 8 cols; x stride 130 float2.
__global__ __launch_bounds__(256) void k_gemm2(const float* __restrict__ w_rel,
                                               const float* __restrict__ w_root,
                                               const float* __restrict__ b2,
                                               float* __restrict__ out, int blk0) {
    extern __shared__ float smem[];
    float*  sWrel  = smem;                      // [128][64]
    float*  sWroot = smem + 128 * 64;
    float2* sXd    = (float2*)(smem + 2 * 128 * 64); // [128][130]
    int t = threadIdx.x;

    for (int i = t; i < 128 * 64 / 4; i += 256) {
        ((float4*)sWrel)[i]  = ((const float4*)w_rel)[i];
        ((float4*)sWroot)[i] = ((const float4*)w_root)[i];
    }
    int row0 = (blk0 + blockIdx.x) * 128;
    for (int idx = t; idx < 128 * 128; idx += 256) {
        int r = idx >> 7, k = idx & 127;
        int grow = row0 + r;
        float v = (grow < NN) ? g_h[(size_t)grow * 128 + k] : 0.f;
        v = fmaxf(v, 0.f);
        sXd[k * 130 + r] = make_float2(v, v);
    }
    __syncthreads();

    int cg = t & 15, rg = t >> 4;   // 16 col groups x 16 row groups (8 rows each)
    unsigned long long acc[8][4];
    #pragma unroll
    for (int i = 0; i < 8; i++)
        #pragma unroll
        for (int j = 0; j < 4; j++) acc[i][j] = 0ull;

    const float* wrp = sWrel + cg * 4;
    const float* wop = sWroot + cg * 4;
    const ulonglong2* xp = (const ulonglong2*)(sXd + rg * 8);   // 16B aligned

    #pragma unroll 4
    for (int k = 0; k < 128; k++) {
        ulonglong2 wr = *(const ulonglong2*)(wrp + k * 64);
        ulonglong2 wo = *(const ulonglong2*)(wop + k * 64);
        #pragma unroll
        for (int q = 0; q < 4; q++) {
            ulonglong2 xv = xp[k * 65 + q];     // rows 2q, 2q+1 (dup'd)
            ffma2(acc[2 * q][0], xv.x, wr.x);
            ffma2(acc[2 * q][1], xv.x, wr.y);
            ffma2(acc[2 * q][2], xv.x, wo.x);
            ffma2(acc[2 * q][3], xv.x, wo.y);
            ffma2(acc[2 * q + 1][0], xv.y, wr.x);
            ffma2(acc[2 * q + 1][1], xv.y, wr.y);
            ffma2(acc[2 * q + 1][2], xv.y, wo.x);
            ffma2(acc[2 * q + 1][3], xv.y, wo.y);
        }
    }

    float4 bias = *(const float4*)(b2 + cg * 4);
    #pragma unroll
    for (int rr = 0; rr < 8; rr++) {
        int row = row0 + rg * 8 + rr;
        if (row >= NN) break;
        float2 a0 = unpack2(acc[rr][0]), a1 = unpack2(acc[rr][1]);
        *(float4*)(g_y2 + (size_t)row * 64 + cg * 4) =
            make_float4(a0.x, a0.y, a1.x, a1.y);
        float2 r0 = unpack2(acc[rr][2]), r1 = unpack2(acc[rr][3]);
        *(float4*)(out + (size_t)row * 64 + cg * 4) =
            make_float4(r0.x + bias.x, r0.y + bias.y, r1.x + bias.z, r1.y + bias.w);
    }
}

// ---------------- gather layer 2: out[n] += sum_{src->n} y2[src] ----------------
__global__ void k_gather2(float* __restrict__ out) {
    int w = (blockIdx.x * blockDim.x + threadIdx.x) >> 5;
    if (w >= NN) return;
    int lane = threadIdx.x & 31;
    int beg = g_rowstart[w], end = g_rowstart[w + 1];
    float2 a0 = make_float2(0, 0), a1 = make_float2(0, 0);
    int j = beg;
    for (; j + 1 < end; j += 2) {
        int s0 = __ldg(&g_csr[j]);
        int s1 = __ldg(&g_csr[j + 1]);
        float2 v0 = *(const float2*)(g_y2 + (size_t)s0 * 64 + lane * 2);
        float2 v1 = *(const float2*)(g_y2 + (size_t)s1 * 64 + lane * 2);
        a0.x += v0.x; a0.y += v0.y;
        a1.x += v1.x; a1.y += v1.y;
    }
    if (j < end) {
        int s = __ldg(&g_csr[j]);
        float2 v = *(const float2*)(g_y2 + (size_t)s * 64 + lane * 2);
        a0.x += v.x; a0.y += v.y;
    }
    float* op = out + (size_t)w * 64 + lane * 2;
    float2 ov = *(float2*)op;
    ov.x += a0.x + a1.x;
    ov.y += a0.y + a1.y;
    *(float2*)op = ov;
}

// ---------------- launch ----------------
extern "C" void kernel_launch(void* const* d_in, const int* in_sizes, int n_in,
                              void* d_out, int out_size) {
    const float* x       = (const float*)d_in[0];
    const int*   ei32    = (const int*)d_in[1];
    const float* w1_rel  = (const float*)d_in[2];
    const float* b1      = (const float*)d_in[3];
    const float* w1_root = (const float*)d_in[4];
    const float* w2_rel  = (const float*)d_in[5];
    const float* b2      = (const float*)d_in[6];
    const float* w2_root = (const float*)d_in[7];
    float*       out     = (float*)d_out;

    static cudaStream_t s_side = nullptr;
    static cudaEvent_t  e_fork = nullptr, e_csr = nullptr, e_g1 = nullptr, e_g1c1 = nullptr;
    if (s_side == nullptr) {
        cudaStreamCreateWithFlags(&s_side, cudaStreamNonBlocking);
        cudaEventCreateWithFlags(&e_fork, cudaEventDisableTiming);
        cudaEventCreateWithFlags(&e_csr,  cudaEventDisableTiming);
        cudaEventCreateWithFlags(&e_g1,   cudaEventDisableTiming);
        cudaEventCreateWithFlags(&e_g1c1, cudaEventDisableTiming);
    }

    const int SMEM1 = 2 * 128 * 128 * 4 + 128 * 66 * 8;   // 198656
    const int SMEM2 = 2 * 128 * 64 * 4 + 128 * 130 * 8;   // 198656
    cudaFuncSetAttribute(k_gemm1, cudaFuncAttributeMaxDynamicSharedMemorySize, SMEM1);
    cudaFuncSetAttribute(k_gemm2, cudaFuncAttributeMaxDynamicSharedMemorySize, SMEM2);

    // fork side stream
    cudaEventRecord(e_fork, 0);
    cudaStreamWaitEvent(s_side, e_fork, 0);

    // issue order: k_gemm1 is the 4th kernel launch (ncu profiles index 3)
    k_init <<<(NN + 255) / 256, 256, 0, s_side>>>(ei32);        // 0
    k_hist <<<(EE + 255) / 256, 256, 0, s_side>>>(ei32);        // 1
    k_scanA<<<(NN + 1023) / 1024, 256, 0, s_side>>>();          // 2
    k_gemm1<<<(NN + 63) / 64, 256, SMEM1>>>(x, w1_rel, w1_root, b1);   // 3  <- profiled
    k_scanB<<<1, 128, 0, s_side>>>();                           // 4
    k_scanC<<<(NN + 255) / 256, 256, 0, s_side>>>();            // 5
    k_fill <<<(EE + 255) / 256, 256, 0, s_side>>>(ei32);        // 6
    cudaEventRecord(e_csr, s_side);
    cudaEventRecord(e_g1, 0);

    // chunk 0 on main: gather1 then gemm2
    cudaStreamWaitEvent(0, e_csr, 0);
    k_gather1<<<(CH0 * 32 + 255) / 256, 256>>>(0, CH0);         // 7
    k_gemm2  <<<CH0 / 128, 256, SMEM2>>>(w2_rel, w2_root, b2, out, 0);   // 8

    // chunk 1 gather on side (needs CSR: program order; gemm1: e_g1)
    cudaStreamWaitEvent(s_side, e_g1, 0);
    k_gather1<<<((NN - CH0) * 32 + 255) / 256, 256, 0, s_side>>>(CH0, NN);   // 9
    cudaEventRecord(e_g1c1, s_side);

    // chunk 1 gemm2 on main after side gather done
    cudaStreamWaitEvent(0, e_g1c1, 0);
    k_gemm2<<<(NN + 127) / 128 - CH0 / 128, 256, SMEM2>>>(w2_rel, w2_root, b2, out, CH0 / 128);  // 10

    // final gather
    k_gather2<<<(NN * 32 + 255) / 256, 256>>>(out);             // 11
}